// round 9
// baseline (speedup 1.0000x reference)
#include <cuda_runtime.h>
#include <cuda_bf16.h>
#include <math.h>
#include <stdint.h>

#define HIDDEN   2048
#define NHEADS   16
#define HDIM     128
#define BATCH    2
#define SEQ      2048
#define BH       (BATCH * NHEADS)
#define MROWS    (BATCH * SEQ)
#define INV_NORM 0.08838834764831845f   // 1/sqrt(128)
#define SM_SHIFT 16.0f

#define EPI_STR  132
// 256x128 tile core: stage = Ah 16K | Al 16K | Bh 8K | Bl 8K = 48KB, 3 stages
#define STG2_B   49152
#define NSTAGE   3
#define SMEM_G2  (NSTAGE * STG2_B)       // 147456

// ===================== scratch (static __device__, no allocation) ============
__device__ __align__(128) float g_scores[(size_t)BH * SEQ * SEQ];   // 512MB

__device__ __align__(128) __nv_bfloat16 g_xh[(size_t)MROWS * HIDDEN];
__device__ __align__(128) __nv_bfloat16 g_xl[(size_t)MROWS * HIDDEN];
__device__ __align__(128) __nv_bfloat16 g_wqh[(size_t)HIDDEN * HIDDEN];
__device__ __align__(128) __nv_bfloat16 g_wql[(size_t)HIDDEN * HIDDEN];
__device__ __align__(128) __nv_bfloat16 g_wkh[(size_t)HIDDEN * HIDDEN];
__device__ __align__(128) __nv_bfloat16 g_wkl[(size_t)HIDDEN * HIDDEN];
__device__ __align__(128) __nv_bfloat16 g_wvh[(size_t)HIDDEN * HIDDEN];
__device__ __align__(128) __nv_bfloat16 g_wvl[(size_t)HIDDEN * HIDDEN];
__device__ __align__(128) __nv_bfloat16 g_wdh[(size_t)HIDDEN * HIDDEN];
__device__ __align__(128) __nv_bfloat16 g_wdl[(size_t)HIDDEN * HIDDEN];

__device__ __align__(128) __nv_bfloat16 g_qh[(size_t)BH * SEQ * HDIM];
__device__ __align__(128) __nv_bfloat16 g_ql[(size_t)BH * SEQ * HDIM];
__device__ __align__(128) __nv_bfloat16 g_kh[(size_t)BH * SEQ * HDIM];
__device__ __align__(128) __nv_bfloat16 g_kl[(size_t)BH * SEQ * HDIM];
__device__ __align__(128) __nv_bfloat16 g_vTh[(size_t)BH * HDIM * SEQ];
__device__ __align__(128) __nv_bfloat16 g_vTl[(size_t)BH * HDIM * SEQ];
__device__ __align__(128) __nv_bfloat16 g_ch[(size_t)MROWS * HIDDEN];
__device__ __align__(128) __nv_bfloat16 g_cl[(size_t)MROWS * HIDDEN];

// ===================== helpers ===============================================
static __device__ __forceinline__ uint32_t s2u(const void* p) {
    uint32_t a;
    asm("{ .reg .u64 t; cvta.to.shared.u64 t, %1; cvt.u32.u64 %0, t; }"
        : "=r"(a) : "l"(p));
    return a;
}
static __device__ __forceinline__ void ldm4(uint32_t (&r)[4], uint32_t addr) {
    asm volatile("ldmatrix.sync.aligned.m8n8.x4.shared.b16 {%0,%1,%2,%3}, [%4];"
                 : "=r"(r[0]), "=r"(r[1]), "=r"(r[2]), "=r"(r[3]) : "r"(addr));
}
static __device__ __forceinline__ void mma16816(float (&c)[4],
                                                const uint32_t (&a)[4],
                                                const uint32_t* b) {
    asm volatile("mma.sync.aligned.m16n8k16.row.col.f32.bf16.bf16.f32 "
                 "{%0,%1,%2,%3}, {%4,%5,%6,%7}, {%8,%9}, {%0,%1,%2,%3};"
                 : "+f"(c[0]), "+f"(c[1]), "+f"(c[2]), "+f"(c[3])
                 : "r"(a[0]), "r"(a[1]), "r"(a[2]), "r"(a[3]),
                   "r"(b[0]), "r"(b[1]));
}
static __device__ __forceinline__ void split_bf(float x, __nv_bfloat16& h,
                                                __nv_bfloat16& l) {
    h = __float2bfloat16(x);
    l = __float2bfloat16(x - __bfloat162float(h));
}
static __device__ __forceinline__ void cpa16(uint32_t so, const void* g) {
    asm volatile("cp.async.cg.shared.global [%0], [%1], 16;" :: "r"(so), "l"(g));
}
static __device__ __forceinline__ uint32_t swz(int row, int c16) {       // 64B rows
    return (uint32_t)(row * 64 + ((c16 ^ ((row >> 1) & 3)) << 4));
}
static __device__ __forceinline__ uint32_t swz128(int row, int c16) {    // 128B rows
    return (uint32_t)(row * 128 + ((c16 ^ (row & 7)) << 4));
}

// one warp's 12-MMA bundle for a 16-row A slab (hi+lo) against cached B frags
static __device__ __forceinline__ void mma_slab(
    float (&accm)[4][4], uint32_t aAddrH, uint32_t aAddrL,
    const uint32_t (&bH)[2][4], const uint32_t (&bL)[2][4]) {
    uint32_t aH4[4], aL4[4];
    ldm4(aH4, aAddrH);
    ldm4(aL4, aAddrL);
#pragma unroll
    for (int ni = 0; ni < 4; ni++) {
        const uint32_t* bh2 = &bH[ni >> 1][(ni & 1) * 2];
        const uint32_t* bl2 = &bL[ni >> 1][(ni & 1) * 2];
        mma16816(accm[ni], aH4, bh2);
        mma16816(accm[ni], aH4, bl2);
        mma16816(accm[ni], aL4, bh2);
    }
}

// ===================== bf16x3 GEMM core, 256x128 tile, 512 threads ===========
// C[256x128] = A[256xK] @ B[128xK]^T. 16 warps: wm=wid&3 (64 rows), wn=wid>>2.
static __device__ __forceinline__ void mma_gemm256(
    const __nv_bfloat16* __restrict__ Ah, const __nv_bfloat16* __restrict__ Al,
    const __nv_bfloat16* __restrict__ Bh, const __nv_bfloat16* __restrict__ Bl,
    int K, int lda, int ldb, float (&acc)[4][4][4]) {
    extern __shared__ char smem[];
    const uint32_t sb = s2u(smem);
    const int tid  = threadIdx.x;
    const int lane = tid & 31;
    const int wid  = tid >> 5;
    const int wm   = wid & 3;
    const int wn   = wid >> 2;
    const int NC   = K >> 5;

    const int arow = tid >> 1;           // 0..255, 2 uint4 per A tile
    const int ac0  = (tid & 1) * 2;
    const int brow = tid >> 2;           // 0..127, 1 uint4 per B tile
    const int bc16 = tid & 3;

#define ISSUE2(cc)                                                             \
    {                                                                          \
        const int _c = (cc);                                                   \
        const uint32_t sbase = sb + (_c % NSTAGE) * STG2_B;                    \
        _Pragma("unroll")                                                      \
        for (int t = 0; t < 2; t++) {                                          \
            const __nv_bfloat16* As = t ? Al : Ah;                             \
            _Pragma("unroll")                                                  \
            for (int u = 0; u < 2; u++) {                                      \
                const int c16 = ac0 + u;                                       \
                const char* g = (const char*)(As + (size_t)arow * lda +        \
                                              _c * 32) + c16 * 16;             \
                cpa16(sbase + t * 16384 + swz(arow, c16), g);                  \
            }                                                                  \
        }                                                                      \
        _Pragma("unroll")                                                      \
        for (int t = 0; t < 2; t++) {                                          \
            const __nv_bfloat16* Bs = t ? Bl : Bh;                             \
            const char* g = (const char*)(Bs + (size_t)brow * ldb +            \
                                          _c * 32) + bc16 * 16;                \
            cpa16(sbase + 32768 + t * 8192 + swz(brow, bc16), g);              \
        }                                                                      \
        asm volatile("cp.async.commit_group;" ::: "memory");                   \
    }

    ISSUE2(0);
    if (NC > 1) ISSUE2(1);

    const int arow_in = lane & 15;
    const int akh     = lane >> 4;
    const int brow_in = ((lane >> 4) << 3) + (lane & 7);
    const int bkh     = (lane >> 3) & 1;

    for (int c = 0; c < NC; c++) {
        if (c + 1 < NC) {
            asm volatile("cp.async.wait_group 1;" ::: "memory");
        } else {
            asm volatile("cp.async.wait_group 0;" ::: "memory");
        }
        __syncthreads();
        if (c + 2 < NC) ISSUE2(c + 2);

        const uint32_t st = sb + (c % NSTAGE) * STG2_B;
#pragma unroll
        for (int kk = 0; kk < 2; kk++) {
            uint32_t bH[2][4], bL[2][4];
#pragma unroll
            for (int nj = 0; nj < 2; nj++) {
                const int row = wn * 32 + nj * 16 + brow_in;
                const uint32_t bd = st + 32768 + swz(row, kk * 2 + bkh);
                ldm4(bH[nj], bd);
                ldm4(bL[nj], bd + 8192);
            }
#pragma unroll
            for (int mi = 0; mi < 4; mi++) {
                const int row = wm * 64 + mi * 16 + arow_in;
                const uint32_t ad = st + swz(row, kk * 2 + akh);
                mma_slab(acc[mi], ad, ad + 16384, bH, bL);
            }
        }
    }
    __syncthreads();
#undef ISSUE2
}

static __device__ __forceinline__ void acc_to_smem256(float (&acc)[4][4][4]) {
    extern __shared__ char smem[];
    float* ep = (float*)smem;
    const int lane = threadIdx.x & 31;
    const int wid  = threadIdx.x >> 5;
    const int wm = wid & 3, wn = wid >> 2;
#pragma unroll
    for (int mi = 0; mi < 4; mi++)
#pragma unroll
        for (int ni = 0; ni < 4; ni++) {
            const int r0 = wm * 64 + mi * 16 + (lane >> 2);
            const int c0 = wn * 32 + ni * 8 + (lane & 3) * 2;
            ep[r0 * EPI_STR + c0]           = acc[mi][ni][0];
            ep[r0 * EPI_STR + c0 + 1]       = acc[mi][ni][1];
            ep[(r0 + 8) * EPI_STR + c0]     = acc[mi][ni][2];
            ep[(r0 + 8) * EPI_STR + c0 + 1] = acc[mi][ni][3];
        }
    __syncthreads();
}

// ===================== fp32 -> bf16 hi/lo split (one launch for all) =========
__global__ void __launch_bounds__(256)
cvt_all_kernel(const float* __restrict__ X,  const float* __restrict__ Wq,
               const float* __restrict__ Wk, const float* __restrict__ Wv,
               const float* __restrict__ Wd) {
    const int bid = blockIdx.x;
    const float* src;
    __nv_bfloat16 *hi, *lo;
    int rel;
    if (bid < 8192)       { src = X;  hi = g_xh;  lo = g_xl;  rel = bid; }
    else {
        const int w = (bid - 8192) >> 12;
        rel = (bid - 8192) & 4095;
        switch (w) {
            case 0:  src = Wq; hi = g_wqh; lo = g_wql; break;
            case 1:  src = Wk; hi = g_wkh; lo = g_wkl; break;
            case 2:  src = Wv; hi = g_wvh; lo = g_wvl; break;
            default: src = Wd; hi = g_wdh; lo = g_wdl; break;
        }
    }
    const int i = rel * 256 + threadIdx.x;
    float4 v = ((const float4*)src)[i];
    __nv_bfloat16 h0, l0, h1, l1, h2, l2, h3, l3;
    split_bf(v.x, h0, l0); split_bf(v.y, h1, l1);
    split_bf(v.z, h2, l2); split_bf(v.w, h3, l3);
    __nv_bfloat162 hv[2] = { __nv_bfloat162(h0, h1), __nv_bfloat162(h2, h3) };
    __nv_bfloat162 lv[2] = { __nv_bfloat162(l0, l1), __nv_bfloat162(l2, l3) };
    *(uint2*)(hi + (size_t)i * 4) = *(uint2*)hv;
    *(uint2*)(lo + (size_t)i * 4) = *(uint2*)lv;
}

// ===================== 1) QKV projection (256-row tiles) =====================
__global__ void __launch_bounds__(512, 1)
qkv_kernel(const float* __restrict__ pbq, const float* __restrict__ pbk,
           const float* __restrict__ pbv) {
    const int mode = blockIdx.z;
    const int m0 = blockIdx.y * 256, n0 = blockIdx.x * 128;
    const __nv_bfloat16* Wh = (mode == 0) ? g_wqh : (mode == 1) ? g_wkh : g_wvh;
    const __nv_bfloat16* Wl = (mode == 0) ? g_wql : (mode == 1) ? g_wkl : g_wvl;
    const float* bias = (mode == 0) ? pbq : (mode == 1) ? pbk : pbv;

    float acc[4][4][4] = {};
    mma_gemm256(g_xh + (size_t)m0 * HIDDEN, g_xl + (size_t)m0 * HIDDEN,
                Wh + (size_t)n0 * HIDDEN, Wl + (size_t)n0 * HIDDEN,
                HIDDEN, HIDDEN, HIDDEN, acc);
    acc_to_smem256(acc);

    extern __shared__ char smem[];
    const float* ep = (const float*)smem;
    const int tid = threadIdx.x;
    const int h = blockIdx.x;

    if (mode == 2) {
        // vT: [bh][d][s]; thread owns one d-column, 64 of the 256 s values
        const int dcol = tid & 127;
        const int q4   = tid >> 7;           // 0..3
        const int b = m0 >> 11;              // 256 | 2048 so single batch
        const float bia = bias[n0 + dcol];
        const size_t base = ((size_t)(b * NHEADS + h) * HDIM + dcol) * SEQ +
                            (m0 & (SEQ - 1)) + q4 * 64;
#pragma unroll 8
        for (int s = 0; s < 64; s += 2) {
            float v0 = ep[(q4 * 64 + s) * EPI_STR + dcol] + bia;
            float v1 = ep[(q4 * 64 + s + 1) * EPI_STR + dcol] + bia;
            __nv_bfloat16 h0, l0, h1, l1;
            split_bf(v0, h0, l0); split_bf(v1, h1, l1);
            *(__nv_bfloat162*)(g_vTh + base + s) = __nv_bfloat162(h0, h1);
            *(__nv_bfloat162*)(g_vTl + base + s) = __nv_bfloat162(l0, l1);
        }
    } else {
        const int r = tid >> 1;              // 0..255
        const int half = tid & 1;
        const int m = m0 + r;
        const int b = m >> 11, s = m & (SEQ - 1);
        __nv_bfloat16* dh = (mode == 0) ? g_qh : g_kh;
        __nv_bfloat16* dl = (mode == 0) ? g_ql : g_kl;
        const size_t base = ((size_t)(b * NHEADS + h) * SEQ + s) * HDIM + half * 64;
        const float* er = ep + r * EPI_STR + half * 64;
        const float* bi = bias + n0 + half * 64;
#pragma unroll 8
        for (int cc = 0; cc < 64; cc += 2) {
            float v0 = er[cc] + bi[cc];
            float v1 = er[cc + 1] + bi[cc + 1];
            __nv_bfloat16 h0, l0, h1, l1;
            split_bf(v0, h0, l0); split_bf(v1, h1, l1);
            *(__nv_bfloat162*)(dh + base + cc) = __nv_bfloat162(h0, h1);
            *(__nv_bfloat162*)(dl + base + cc) = __nv_bfloat162(l0, l1);
        }
    }
}

// ===================== 2) scores = alibi + inv_norm * Q K^T ==================
__global__ void __launch_bounds__(512, 1)
scores_kernel(const float* __restrict__ alibi) {
    const int z = blockIdx.z;
    const int m0 = blockIdx.y * 256, n0 = blockIdx.x * 128;
    const size_t zo = (size_t)z * SEQ * HDIM;

    float acc[4][4][4] = {};
    mma_gemm256(g_qh + zo + (size_t)m0 * HDIM, g_ql + zo + (size_t)m0 * HDIM,
                g_kh + zo + (size_t)n0 * HDIM, g_kl + zo + (size_t)n0 * HDIM,
                HDIM, HDIM, HDIM, acc);
    acc_to_smem256(acc);

    extern __shared__ char smem[];
    const float* ep = (const float*)smem;
    const int tid = threadIdx.x;
    const int r = tid >> 1, half = tid & 1;
    const float* al = alibi + (size_t)z * SEQ + n0 + half * 64;
    float* C = g_scores + (size_t)z * SEQ * SEQ +
               (size_t)(m0 + r) * SEQ + n0 + half * 64;
    const float* er = ep + r * EPI_STR + half * 64;
#pragma unroll 4
    for (int cc = 0; cc < 64; cc += 4) {
        float4 av = *(const float4*)(al + cc);
        float4 v;
        v.x = av.x + INV_NORM * er[cc + 0];
        v.y = av.y + INV_NORM * er[cc + 1];
        v.z = av.z + INV_NORM * er[cc + 2];
        v.w = av.w + INV_NORM * er[cc + 3];
        *(float4*)(C + cc) = v;
    }
}

// ===================== 3) ctx = softmax(S) @ V, pipelined convert ============
#define CS_P    32768
#define CS_V    65536
#define CROWSUM 114688
#define CSMEM   115712

__global__ void __launch_bounds__(256, 2)
ctx_kernel() {
    extern __shared__ char smem[];
    const uint32_t sb = s2u(smem);
    const int tid  = threadIdx.x;
    const int lane = tid & 31;
    const int wid  = tid >> 5;
    const int wm   = wid & 1;
    const int wn   = wid >> 1;
    const int z    = blockIdx.z;
    const int m0   = blockIdx.y * 128;
    const size_t so_base = (size_t)z * SEQ * SEQ + (size_t)m0 * SEQ;
    const size_t vo = (size_t)z * HDIM * SEQ;
    const int NC = SEQ / 32;     // 64

    const int crow = tid >> 1;
    const int chf  = tid & 1;

#define CISSUE(cc, vb_)                                                        \
    {                                                                          \
        const int _c = (cc);                                                   \
        const uint32_t sbS = sb + ((_c) & 1) * 16384;                          \
        const uint32_t sbV = sb + CS_V + (vb_) * 16384;                        \
        const char* gs = (const char*)(g_scores + so_base +                    \
                                       (size_t)crow * SEQ) + _c * 128;         \
        _Pragma("unroll")                                                      \
        for (int u = 0; u < 4; u++) {                                          \
            const int c16 = chf * 4 + u;                                       \
            cpa16(sbS + swz128(crow, c16), gs + c16 * 16);                     \
        }                                                                      \
        const char* gvh = (const char*)(g_vTh + vo + (size_t)crow * SEQ) +     \
                          _c * 64;                                             \
        const char* gvl = (const char*)(g_vTl + vo + (size_t)crow * SEQ) +     \
                          _c * 64;                                             \
        _Pragma("unroll")                                                      \
        for (int u = 0; u < 2; u++) {                                          \
            const int c16 = chf * 2 + u;                                       \
            cpa16(sbV + swz(crow, c16),        gvh + c16 * 16);                \
            cpa16(sbV + 8192 + swz(crow, c16), gvl + c16 * 16);                \
        }                                                                      \
        asm volatile("cp.async.commit_group;" ::: "memory");                   \
    }

#define CCONVERT(cc)                                                           \
    {                                                                          \
        const int _b = (cc) & 1;                                               \
        _Pragma("unroll")                                                      \
        for (int u = 0; u < 4; u++) {                                          \
            const int c16 = chf * 4 + u;                                       \
            float4 s = *(const float4*)(smem + _b * 16384 +                    \
                                        swz128(crow, c16));                    \
            float p0 = __expf(s.x - SM_SHIFT);                                 \
            float p1 = __expf(s.y - SM_SHIFT);                                 \
            float p2 = __expf(s.z - SM_SHIFT);                                 \
            float p3 = __expf(s.w - SM_SHIFT);                                 \
            rsum += (p0 + p1) + (p2 + p3);                                     \
            __nv_bfloat16 h0, l0, h1, l1, h2, l2, h3, l3;                      \
            split_bf(p0, h0, l0); split_bf(p1, h1, l1);                        \
            split_bf(p2, h2, l2); split_bf(p3, h3, l3);                        \
            __nv_bfloat162 hv[2] = { __nv_bfloat162(h0, h1),                   \
                                     __nv_bfloat162(h2, h3) };                 \
            __nv_bfloat162 lv[2] = { __nv_bfloat162(l0, l1),                   \
                                     __nv_bfloat162(l2, l3) };                 \
            const uint32_t da = CS_P + _b * 16384 + swz(crow, c16 >> 1) +      \
                                (c16 & 1) * 8;                                 \
            *(uint2*)(smem + da)        = *(uint2*)hv;                         \
            *(uint2*)(smem + da + 8192) = *(uint2*)lv;                         \
        }                                                                      \
    }

    const int arow_in = lane & 15;
    const int akh     = lane >> 4;
    const int brow_in = ((lane >> 4) << 3) + (lane & 7);
    const int bkh     = (lane >> 3) & 1;

    float acc[4][4][4] = {};
    float rsum = 0.f;

    CISSUE(0, 0);
    CISSUE(1, 1);
    asm volatile("cp.async.wait_group 1;" ::: "memory");
    __syncthreads();
    CCONVERT(0);

    int vb0 = 0;
    int vb2 = 2;
    for (int c = 0; c < NC; c++) {
        asm volatile("cp.async.wait_group 0;" ::: "memory");
        __syncthreads();
        if (c + 2 < NC) CISSUE(c + 2, vb2);
        if (c + 1 < NC) CCONVERT(c + 1);

        const uint32_t pA = sb + CS_P + (c & 1) * 16384;
        const uint32_t pB = sb + CS_V + vb0 * 16384;
#pragma unroll
        for (int kk = 0; kk < 2; kk++) {
            uint32_t bH[2][4], bL[2][4];
#pragma unroll
            for (int nj = 0; nj < 2; nj++) {
                const int row = wn * 32 + nj * 16 + brow_in;
                const uint32_t bd = swz(row, kk * 2 + bkh);
                ldm4(bH[nj], pB + bd);
                ldm4(bL[nj], pB + 8192 + bd);
            }
#pragma unroll
            for (int mi = 0; mi < 4; mi++) {
                const int row = wm * 64 + mi * 16 + arow_in;
                const uint32_t ad = swz(row, kk * 2 + akh);
                mma_slab(acc[mi], pA + ad, pA + 8192 + ad, bH, bL);
            }
        }
        vb0 = (vb0 == 2) ? 0 : vb0 + 1;
        vb2 = (vb2 == 2) ? 0 : vb2 + 1;
    }
#undef CISSUE
#undef CCONVERT

    float* rs = (float*)(smem + CROWSUM);
    __syncthreads();
    rs[chf * 128 + crow] = rsum;
    __syncthreads();
#pragma unroll
    for (int mi = 0; mi < 4; mi++) {
        const int r0 = wm * 64 + mi * 16 + (lane >> 2);
        const float inv0 = 1.0f / (rs[r0] + rs[128 + r0]);
        const float inv1 = 1.0f / (rs[r0 + 8] + rs[128 + r0 + 8]);
#pragma unroll
        for (int ni = 0; ni < 4; ni++) {
            acc[mi][ni][0] *= inv0;
            acc[mi][ni][1] *= inv0;
            acc[mi][ni][2] *= inv1;
            acc[mi][ni][3] *= inv1;
        }
    }
    __syncthreads();
    // 128-row epilogue staging (reuse of layout helper inline)
    {
        float* ep = (float*)smem;
        const int wm2 = wid & 1, wn2 = wid >> 1;
#pragma unroll
        for (int mi = 0; mi < 4; mi++)
#pragma unroll
            for (int ni = 0; ni < 4; ni++) {
                const int r0 = wm2 * 64 + mi * 16 + (lane >> 2);
                const int c0 = wn2 * 32 + ni * 8 + (lane & 3) * 2;
                ep[r0 * EPI_STR + c0]           = acc[mi][ni][0];
                ep[r0 * EPI_STR + c0 + 1]       = acc[mi][ni][1];
                ep[(r0 + 8) * EPI_STR + c0]     = acc[mi][ni][2];
                ep[(r0 + 8) * EPI_STR + c0 + 1] = acc[mi][ni][3];
            }
        __syncthreads();
    }

    const float* ep = (const float*)smem;
    const int r = tid >> 1, half = tid & 1;
    const int b = z / NHEADS, h = z % NHEADS;
    const size_t base = ((size_t)(b * SEQ + m0 + r)) * HIDDEN +
                        h * HDIM + half * 64;
    const float* er = ep + r * EPI_STR + half * 64;
#pragma unroll 8
    for (int cc = 0; cc < 64; cc += 2) {
        __nv_bfloat16 h0, l0, h1, l1;
        split_bf(er[cc], h0, l0); split_bf(er[cc + 1], h1, l1);
        *(__nv_bfloat162*)(g_ch + base + cc) = __nv_bfloat162(h0, h1);
        *(__nv_bfloat162*)(g_cl + base + cc) = __nv_bfloat162(l0, l1);
    }
}

// ===================== 4) out = ctx @ Wd^T + bd + residual ===================
__global__ void __launch_bounds__(512, 1)
out_kernel(const float* __restrict__ bd, const float* __restrict__ residual,
           float* __restrict__ outp) {
    const int m0 = blockIdx.y * 256, n0 = blockIdx.x * 128;

    float acc[4][4][4] = {};
    mma_gemm256(g_ch + (size_t)m0 * HIDDEN, g_cl + (size_t)m0 * HIDDEN,
                g_wdh + (size_t)n0 * HIDDEN, g_wdl + (size_t)n0 * HIDDEN,
                HIDDEN, HIDDEN, HIDDEN, acc);
    acc_to_smem256(acc);

    extern __shared__ char smem[];
    const float* ep = (const float*)smem;
    const int tid = threadIdx.x;
    const int r = tid >> 1, half = tid & 1;
    const size_t idx = (size_t)(m0 + r) * HIDDEN + n0 + half * 64;
    const float* er = ep + r * EPI_STR + half * 64;
    const float* bi = bd + n0 + half * 64;
    const float* rs = residual + idx;
    float* dst = outp + idx;
#pragma unroll 4
    for (int cc = 0; cc < 64; cc += 4) {
        float4 bv = *(const float4*)(bi + cc);
        float4 rv = *(const float4*)(rs + cc);
        float4 v;
        v.x = er[cc + 0] + bv.x + rv.x;
        v.y = er[cc + 1] + bv.y + rv.y;
        v.z = er[cc + 2] + bv.z + rv.z;
        v.w = er[cc + 3] + bv.w + rv.w;
        *(float4*)(dst + cc) = v;
    }
}

// ===================== launch =================================================
extern "C" void kernel_launch(void* const* d_in, const int* in_sizes, int n_in,
                              void* d_out, int out_size) {
    const float* X        = (const float*)d_in[0];
    const float* residual = (const float*)d_in[1];
    const float* alibi    = (const float*)d_in[2];
    const float* Wq = (const float*)d_in[3];  const float* bq = (const float*)d_in[4];
    const float* Wk = (const float*)d_in[5];  const float* bk = (const float*)d_in[6];
    const float* Wv = (const float*)d_in[7];  const float* bv = (const float*)d_in[8];
    const float* Wd = (const float*)d_in[9];  const float* bd = (const float*)d_in[10];
    float* out = (float*)d_out;

    cudaFuncSetAttribute(qkv_kernel, cudaFuncAttributeMaxDynamicSharedMemorySize, SMEM_G2);
    cudaFuncSetAttribute(scores_kernel, cudaFuncAttributeMaxDynamicSharedMemorySize, SMEM_G2);
    cudaFuncSetAttribute(ctx_kernel, cudaFuncAttributeMaxDynamicSharedMemorySize, CSMEM);
    cudaFuncSetAttribute(out_kernel, cudaFuncAttributeMaxDynamicSharedMemorySize, SMEM_G2);

    cvt_all_kernel<<<8192 + 4 * 4096, 256>>>(X, Wq, Wk, Wv, Wd);

    qkv_kernel<<<dim3(16, 16, 3), 512, SMEM_G2>>>(bq, bk, bv);
    scores_kernel<<<dim3(16, 8, 32), 512, SMEM_G2>>>(alibi);
    ctx_kernel<<<dim3(1, 16, 32), 256, CSMEM>>>();
    out_kernel<<<dim3(16, 16), 512, SMEM_G2>>>(bd, residual, out);
}

// round 10
// speedup vs baseline: 1.2902x; 1.2902x over previous
#include <cuda_runtime.h>
#include <cuda_bf16.h>
#include <math.h>
#include <stdint.h>

#define HIDDEN   2048
#define NHEADS   16
#define HDIM     128
#define BATCH    2
#define SEQ      2048
#define BH       (BATCH * NHEADS)
#define MROWS    (BATCH * SEQ)
#define INV_NORM 0.08838834764831845f   // 1/sqrt(128)
#define SM_SHIFT 16.0f

#define KB        32
#define STAGE_B   32768
#define NSTAGE    3
#define EPI_STR   132
#define SMEM_DYN  (NSTAGE * STAGE_B)     // 98304

// ctx: stage buffers [0,98304) + rowsum[128] at 98304
#define CTX_RS    98304
#define CTX_SMEM  98816

// ===================== scratch (static __device__, no allocation) ============
__device__ __align__(128) __nv_bfloat16 g_ph[(size_t)BH * SEQ * SEQ];   // 256MB
__device__ __align__(128) __nv_bfloat16 g_pl[(size_t)BH * SEQ * SEQ];   // 256MB
__device__ __align__(128) float g_psum[(size_t)BH * 16 * SEQ];          // 4MB

__device__ __align__(128) __nv_bfloat16 g_xh[(size_t)MROWS * HIDDEN];
__device__ __align__(128) __nv_bfloat16 g_xl[(size_t)MROWS * HIDDEN];
__device__ __align__(128) __nv_bfloat16 g_wqh[(size_t)HIDDEN * HIDDEN];
__device__ __align__(128) __nv_bfloat16 g_wql[(size_t)HIDDEN * HIDDEN];
__device__ __align__(128) __nv_bfloat16 g_wkh[(size_t)HIDDEN * HIDDEN];
__device__ __align__(128) __nv_bfloat16 g_wkl[(size_t)HIDDEN * HIDDEN];
__device__ __align__(128) __nv_bfloat16 g_wvh[(size_t)HIDDEN * HIDDEN];
__device__ __align__(128) __nv_bfloat16 g_wvl[(size_t)HIDDEN * HIDDEN];
__device__ __align__(128) __nv_bfloat16 g_wdh[(size_t)HIDDEN * HIDDEN];
__device__ __align__(128) __nv_bfloat16 g_wdl[(size_t)HIDDEN * HIDDEN];

__device__ __align__(128) __nv_bfloat16 g_qh[(size_t)BH * SEQ * HDIM];
__device__ __align__(128) __nv_bfloat16 g_ql[(size_t)BH * SEQ * HDIM];
__device__ __align__(128) __nv_bfloat16 g_kh[(size_t)BH * SEQ * HDIM];
__device__ __align__(128) __nv_bfloat16 g_kl[(size_t)BH * SEQ * HDIM];
__device__ __align__(128) __nv_bfloat16 g_vTh[(size_t)BH * HDIM * SEQ];
__device__ __align__(128) __nv_bfloat16 g_vTl[(size_t)BH * HDIM * SEQ];
__device__ __align__(128) __nv_bfloat16 g_ch[(size_t)MROWS * HIDDEN];
__device__ __align__(128) __nv_bfloat16 g_cl[(size_t)MROWS * HIDDEN];

// ===================== helpers ===============================================
static __device__ __forceinline__ uint32_t s2u(const void* p) {
    uint32_t a;
    asm("{ .reg .u64 t; cvta.to.shared.u64 t, %1; cvt.u32.u64 %0, t; }"
        : "=r"(a) : "l"(p));
    return a;
}
static __device__ __forceinline__ void ldm4(uint32_t (&r)[4], uint32_t addr) {
    asm volatile("ldmatrix.sync.aligned.m8n8.x4.shared.b16 {%0,%1,%2,%3}, [%4];"
                 : "=r"(r[0]), "=r"(r[1]), "=r"(r[2]), "=r"(r[3]) : "r"(addr));
}
static __device__ __forceinline__ void mma16816(float (&c)[4],
                                                const uint32_t (&a)[4],
                                                const uint32_t* b) {
    asm volatile("mma.sync.aligned.m16n8k16.row.col.f32.bf16.bf16.f32 "
                 "{%0,%1,%2,%3}, {%4,%5,%6,%7}, {%8,%9}, {%0,%1,%2,%3};"
                 : "+f"(c[0]), "+f"(c[1]), "+f"(c[2]), "+f"(c[3])
                 : "r"(a[0]), "r"(a[1]), "r"(a[2]), "r"(a[3]),
                   "r"(b[0]), "r"(b[1]));
}
static __device__ __forceinline__ void split_bf(float x, __nv_bfloat16& h,
                                                __nv_bfloat16& l) {
    h = __float2bfloat16(x);
    l = __float2bfloat16(x - __bfloat162float(h));
}
static __device__ __forceinline__ void cpa16(uint32_t so, const void* g) {
    asm volatile("cp.async.cg.shared.global [%0], [%1], 16;" :: "r"(so), "l"(g));
}
static __device__ __forceinline__ uint32_t swz(int row, int c16) {       // 64B rows
    return (uint32_t)(row * 64 + ((c16 ^ ((row >> 1) & 3)) << 4));
}

// one warp's 12-MMA bundle for a 16-row A slab (hi+lo) against cached B frags
static __device__ __forceinline__ void mma_slab(
    float (&accm)[4][4], uint32_t aAddrH, uint32_t aAddrL,
    const uint32_t (&bH)[2][4], const uint32_t (&bL)[2][4]) {
    uint32_t aH4[4], aL4[4];
    ldm4(aH4, aAddrH);
    ldm4(aL4, aAddrL);
#pragma unroll
    for (int ni = 0; ni < 4; ni++) {
        const uint32_t* bh2 = &bH[ni >> 1][(ni & 1) * 2];
        const uint32_t* bl2 = &bL[ni >> 1][(ni & 1) * 2];
        mma16816(accm[ni], aH4, bh2);
        mma16816(accm[ni], aH4, bl2);
        mma16816(accm[ni], aL4, bh2);
    }
}

// ===================== bf16x3 mma.sync GEMM core (128x128, 256 thr) ==========
static __device__ __forceinline__ void mma_gemm(
    const __nv_bfloat16* __restrict__ Ah, const __nv_bfloat16* __restrict__ Al,
    const __nv_bfloat16* __restrict__ Bh, const __nv_bfloat16* __restrict__ Bl,
    int K, int lda, int ldb, float (&acc)[4][4][4]) {
    extern __shared__ char smem[];
    const uint32_t sb = s2u(smem);
    const int tid  = threadIdx.x;
    const int lane = tid & 31;
    const int wid  = tid >> 5;
    const int wm   = wid & 1;
    const int wn   = wid >> 1;
    const int NC   = K >> 5;

    const __nv_bfloat16* srcs[4] = { Ah, Al, Bh, Bl };
    const int lds[4] = { lda, lda, ldb, ldb };
    const int lrow = tid >> 2;
    const int lc16 = tid & 3;

#define ISSUE(cc)                                                              \
    {                                                                          \
        const int _c = (cc);                                                   \
        const uint32_t sbase = sb + (_c % NSTAGE) * STAGE_B;                   \
        _Pragma("unroll")                                                      \
        for (int mat = 0; mat < 4; mat++) {                                    \
            _Pragma("unroll")                                                  \
            for (int rep = 0; rep < 2; rep++) {                                \
                const int row = lrow + rep * 64;                               \
                const char* g = (const char*)(srcs[mat] +                      \
                                  (size_t)row * lds[mat] + _c * KB) + lc16*16; \
                const uint32_t so = sbase + mat * 8192 + swz(row, lc16);       \
                cpa16(so, g);                                                  \
            }                                                                  \
        }                                                                      \
        asm volatile("cp.async.commit_group;" ::: "memory");                   \
    }

    ISSUE(0);
    if (NC > 1) ISSUE(1);

    const int arow_in = lane & 15;
    const int akh     = lane >> 4;
    const int brow_in = ((lane >> 4) << 3) + (lane & 7);
    const int bkh     = (lane >> 3) & 1;

    for (int c = 0; c < NC; c++) {
        if (c + 1 < NC) {
            asm volatile("cp.async.wait_group 1;" ::: "memory");
        } else {
            asm volatile("cp.async.wait_group 0;" ::: "memory");
        }
        __syncthreads();
        if (c + 2 < NC) ISSUE(c + 2);

        const uint32_t st = sb + (c % NSTAGE) * STAGE_B;
#pragma unroll
        for (int kk = 0; kk < 2; kk++) {
            uint32_t bH[2][4], bL[2][4];
#pragma unroll
            for (int nj = 0; nj < 2; nj++) {
                const int row = wn * 32 + nj * 16 + brow_in;
                const uint32_t bd = st + 16384 + swz(row, kk * 2 + bkh);
                ldm4(bH[nj], bd);
                ldm4(bL[nj], bd + 8192);
            }
#pragma unroll
            for (int mi = 0; mi < 4; mi++) {
                const int row = wm * 64 + mi * 16 + arow_in;
                const uint32_t ad = st + swz(row, kk * 2 + akh);
                mma_slab(acc[mi], ad, ad + 8192, bH, bL);
            }
        }
    }
    __syncthreads();
#undef ISSUE
}

static __device__ __forceinline__ void acc_to_smem(float (&acc)[4][4][4]) {
    extern __shared__ char smem[];
    float* ep = (float*)smem;
    const int lane = threadIdx.x & 31;
    const int wid  = threadIdx.x >> 5;
    const int wm = wid & 1, wn = wid >> 1;
#pragma unroll
    for (int mi = 0; mi < 4; mi++)
#pragma unroll
        for (int ni = 0; ni < 4; ni++) {
            const int r0 = wm * 64 + mi * 16 + (lane >> 2);
            const int c0 = wn * 32 + ni * 8 + (lane & 3) * 2;
            ep[r0 * EPI_STR + c0]           = acc[mi][ni][0];
            ep[r0 * EPI_STR + c0 + 1]       = acc[mi][ni][1];
            ep[(r0 + 8) * EPI_STR + c0]     = acc[mi][ni][2];
            ep[(r0 + 8) * EPI_STR + c0 + 1] = acc[mi][ni][3];
        }
    __syncthreads();
}

// ===================== fp32 -> bf16 hi/lo split (one launch for all) =========
__global__ void __launch_bounds__(256)
cvt_all_kernel(const float* __restrict__ X,  const float* __restrict__ Wq,
               const float* __restrict__ Wk, const float* __restrict__ Wv,
               const float* __restrict__ Wd) {
    const int bid = blockIdx.x;
    const float* src;
    __nv_bfloat16 *hi, *lo;
    int rel;
    if (bid < 8192)       { src = X;  hi = g_xh;  lo = g_xl;  rel = bid; }
    else {
        const int w = (bid - 8192) >> 12;
        rel = (bid - 8192) & 4095;
        switch (w) {
            case 0:  src = Wq; hi = g_wqh; lo = g_wql; break;
            case 1:  src = Wk; hi = g_wkh; lo = g_wkl; break;
            case 2:  src = Wv; hi = g_wvh; lo = g_wvl; break;
            default: src = Wd; hi = g_wdh; lo = g_wdl; break;
        }
    }
    const int i = rel * 256 + threadIdx.x;
    float4 v = ((const float4*)src)[i];
    __nv_bfloat16 h0, l0, h1, l1, h2, l2, h3, l3;
    split_bf(v.x, h0, l0); split_bf(v.y, h1, l1);
    split_bf(v.z, h2, l2); split_bf(v.w, h3, l3);
    __nv_bfloat162 hv[2] = { __nv_bfloat162(h0, h1), __nv_bfloat162(h2, h3) };
    __nv_bfloat162 lv[2] = { __nv_bfloat162(l0, l1), __nv_bfloat162(l2, l3) };
    *(uint2*)(hi + (size_t)i * 4) = *(uint2*)hv;
    *(uint2*)(lo + (size_t)i * 4) = *(uint2*)lv;
}

// ===================== 1) QKV projection =====================================
__global__ void __launch_bounds__(256, 2)
qkv_kernel(const float* __restrict__ pbq, const float* __restrict__ pbk,
           const float* __restrict__ pbv) {
    const int mode = blockIdx.z;
    const int m0 = blockIdx.y * 128, n0 = blockIdx.x * 128;
    const __nv_bfloat16* Wh = (mode == 0) ? g_wqh : (mode == 1) ? g_wkh : g_wvh;
    const __nv_bfloat16* Wl = (mode == 0) ? g_wql : (mode == 1) ? g_wkl : g_wvl;
    const float* bias = (mode == 0) ? pbq : (mode == 1) ? pbk : pbv;

    float acc[4][4][4] = {};
    mma_gemm(g_xh + (size_t)m0 * HIDDEN, g_xl + (size_t)m0 * HIDDEN,
             Wh + (size_t)n0 * HIDDEN, Wl + (size_t)n0 * HIDDEN,
             HIDDEN, HIDDEN, HIDDEN, acc);
    acc_to_smem(acc);

    extern __shared__ char smem[];
    const float* ep = (const float*)smem;
    const int tid = threadIdx.x;
    const int half = tid & 1;
    const int h = blockIdx.x;

    if (mode == 2) {
        const int dcol = tid >> 1;
        const int b = m0 >> 11;
        const float bia = bias[n0 + dcol];
        const size_t base = ((size_t)(b * NHEADS + h) * HDIM + dcol) * SEQ +
                            (m0 & (SEQ - 1)) + half * 64;
#pragma unroll 8
        for (int s = 0; s < 64; s += 2) {
            float v0 = ep[(half * 64 + s) * EPI_STR + dcol] + bia;
            float v1 = ep[(half * 64 + s + 1) * EPI_STR + dcol] + bia;
            __nv_bfloat16 h0, l0, h1, l1;
            split_bf(v0, h0, l0); split_bf(v1, h1, l1);
            *(__nv_bfloat162*)(g_vTh + base + s) = __nv_bfloat162(h0, h1);
            *(__nv_bfloat162*)(g_vTl + base + s) = __nv_bfloat162(l0, l1);
        }
    } else {
        const int r = tid >> 1;
        const int m = m0 + r;
        const int b = m >> 11, s = m & (SEQ - 1);
        __nv_bfloat16* dh = (mode == 0) ? g_qh : g_kh;
        __nv_bfloat16* dl = (mode == 0) ? g_ql : g_kl;
        const size_t base = ((size_t)(b * NHEADS + h) * SEQ + s) * HDIM + half * 64;
        const float* er = ep + r * EPI_STR + half * 64;
        const float* bi = bias + n0 + half * 64;
#pragma unroll 8
        for (int cc = 0; cc < 64; cc += 2) {
            float v0 = er[cc] + bi[cc];
            float v1 = er[cc + 1] + bi[cc + 1];
            __nv_bfloat16 h0, l0, h1, l1;
            split_bf(v0, h0, l0); split_bf(v1, h1, l1);
            *(__nv_bfloat162*)(dh + base + cc) = __nv_bfloat162(h0, h1);
            *(__nv_bfloat162*)(dl + base + cc) = __nv_bfloat162(l0, l1);
        }
    }
}

// ===================== 2) scores -> P = exp(s-16) hi/lo + partial row sums ===
__global__ void __launch_bounds__(256, 2)
scores_kernel(const float* __restrict__ alibi) {
    const int z = blockIdx.z;
    const int m0 = blockIdx.y * 128, n0 = blockIdx.x * 128;
    const size_t zo = (size_t)z * SEQ * HDIM;

    float acc[4][4][4] = {};
    mma_gemm(g_qh + zo + (size_t)m0 * HDIM, g_ql + zo + (size_t)m0 * HDIM,
             g_kh + zo + (size_t)n0 * HDIM, g_kl + zo + (size_t)n0 * HDIM,
             HDIM, HDIM, HDIM, acc);
    acc_to_smem(acc);

    extern __shared__ char smem[];
    const float* ep = (const float*)smem;
    const int tid = threadIdx.x;
    const int r = tid >> 1, half = tid & 1;
    const float* al = alibi + (size_t)z * SEQ + n0 + half * 64;
    const size_t prow = (size_t)z * SEQ * SEQ + (size_t)(m0 + r) * SEQ +
                        n0 + half * 64;
    const float* er = ep + r * EPI_STR + half * 64;

    float lsum = 0.f;
#pragma unroll 4
    for (int cc = 0; cc < 64; cc += 4) {
        float4 av = *(const float4*)(al + cc);
        float p0 = __expf(av.x + INV_NORM * er[cc + 0] - SM_SHIFT);
        float p1 = __expf(av.y + INV_NORM * er[cc + 1] - SM_SHIFT);
        float p2 = __expf(av.z + INV_NORM * er[cc + 2] - SM_SHIFT);
        float p3 = __expf(av.w + INV_NORM * er[cc + 3] - SM_SHIFT);
        lsum += (p0 + p1) + (p2 + p3);
        __nv_bfloat16 h0, l0, h1, l1, h2, l2, h3, l3;
        split_bf(p0, h0, l0); split_bf(p1, h1, l1);
        split_bf(p2, h2, l2); split_bf(p3, h3, l3);
        __nv_bfloat162 hv[2] = { __nv_bfloat162(h0, h1), __nv_bfloat162(h2, h3) };
        __nv_bfloat162 lv[2] = { __nv_bfloat162(l0, l1), __nv_bfloat162(l2, l3) };
        *(uint2*)(g_ph + prow + cc) = *(uint2*)hv;
        *(uint2*)(g_pl + prow + cc) = *(uint2*)lv;
    }
    // combine the two 64-col halves (adjacent lanes) and store partial sum
    lsum += __shfl_xor_sync(0xffffffffu, lsum, 1);
    if (half == 0)
        g_psum[((size_t)z * 16 + blockIdx.x) * SEQ + m0 + r] = lsum;
}

// ===================== 3) ctx = P @ V, normalized ============================
__global__ void __launch_bounds__(256, 2)
ctx_kernel() {
    extern __shared__ char smem[];
    const int tid = threadIdx.x;
    const int z = blockIdx.z;
    const int m0 = blockIdx.y * 128;

    // reduce 16 partial sums per row into smem rowsum[128]
    {
        const int row = tid >> 1, half = tid & 1;
        const float* ps = g_psum + (size_t)z * 16 * SEQ + m0 + row;
        float s = 0.f;
#pragma unroll
        for (int nb = 0; nb < 8; nb++) s += ps[(size_t)(half * 8 + nb) * SEQ];
        s += __shfl_xor_sync(0xffffffffu, s, 1);
        ((float*)(smem + CTX_RS))[row] = s;   // both halves write same value
    }
    // (visibility guaranteed by syncthreads inside mma_gemm before use)

    const size_t po = (size_t)z * SEQ * SEQ + (size_t)m0 * SEQ;
    const size_t vo = (size_t)z * HDIM * SEQ;
    float acc[4][4][4] = {};
    mma_gemm(g_ph + po, g_pl + po, g_vTh + vo, g_vTl + vo,
             SEQ, SEQ, SEQ, acc);

    // normalize accumulators by 1/rowsum
    const int lane = tid & 31, wid = tid >> 5;
    const int wm = wid & 1;
    const float* rsm = (const float*)(smem + CTX_RS);
#pragma unroll
    for (int mi = 0; mi < 4; mi++) {
        const int r0 = wm * 64 + mi * 16 + (lane >> 2);
        const float inv0 = 1.0f / rsm[r0];
        const float inv1 = 1.0f / rsm[r0 + 8];
#pragma unroll
        for (int ni = 0; ni < 4; ni++) {
            acc[mi][ni][0] *= inv0;
            acc[mi][ni][1] *= inv0;
            acc[mi][ni][2] *= inv1;
            acc[mi][ni][3] *= inv1;
        }
    }
    acc_to_smem(acc);

    const float* ep = (const float*)smem;
    const int r = tid >> 1, half = tid & 1;
    const int b = z / NHEADS, h = z % NHEADS;
    const size_t base = ((size_t)(b * SEQ + m0 + r)) * HIDDEN +
                        h * HDIM + half * 64;
    const float* er = ep + r * EPI_STR + half * 64;
#pragma unroll 8
    for (int cc = 0; cc < 64; cc += 2) {
        __nv_bfloat16 h0, l0, h1, l1;
        split_bf(er[cc], h0, l0); split_bf(er[cc + 1], h1, l1);
        *(__nv_bfloat162*)(g_ch + base + cc) = __nv_bfloat162(h0, h1);
        *(__nv_bfloat162*)(g_cl + base + cc) = __nv_bfloat162(l0, l1);
    }
}

// ===================== 4) out = ctx @ Wd^T + bd + residual ===================
__global__ void __launch_bounds__(256, 2)
out_kernel(const float* __restrict__ bd, const float* __restrict__ residual,
           float* __restrict__ outp) {
    const int m0 = blockIdx.y * 128, n0 = blockIdx.x * 128;

    float acc[4][4][4] = {};
    mma_gemm(g_ch + (size_t)m0 * HIDDEN, g_cl + (size_t)m0 * HIDDEN,
             g_wdh + (size_t)n0 * HIDDEN, g_wdl + (size_t)n0 * HIDDEN,
             HIDDEN, HIDDEN, HIDDEN, acc);
    acc_to_smem(acc);

    extern __shared__ char smem[];
    const float* ep = (const float*)smem;
    const int tid = threadIdx.x;
    const int r = tid >> 1, half = tid & 1;
    const size_t idx = (size_t)(m0 + r) * HIDDEN + n0 + half * 64;
    const float* er = ep + r * EPI_STR + half * 64;
    const float* bi = bd + n0 + half * 64;
    const float* rs = residual + idx;
    float* dst = outp + idx;
#pragma unroll 4
    for (int cc = 0; cc < 64; cc += 4) {
        float4 bv = *(const float4*)(bi + cc);
        float4 rv = *(const float4*)(rs + cc);
        float4 v;
        v.x = er[cc + 0] + bv.x + rv.x;
        v.y = er[cc + 1] + bv.y + rv.y;
        v.z = er[cc + 2] + bv.z + rv.z;
        v.w = er[cc + 3] + bv.w + rv.w;
        *(float4*)(dst + cc) = v;
    }
}

// ===================== launch =================================================
extern "C" void kernel_launch(void* const* d_in, const int* in_sizes, int n_in,
                              void* d_out, int out_size) {
    const float* X        = (const float*)d_in[0];
    const float* residual = (const float*)d_in[1];
    const float* alibi    = (const float*)d_in[2];
    const float* Wq = (const float*)d_in[3];  const float* bq = (const float*)d_in[4];
    const float* Wk = (const float*)d_in[5];  const float* bk = (const float*)d_in[6];
    const float* Wv = (const float*)d_in[7];  const float* bv = (const float*)d_in[8];
    const float* Wd = (const float*)d_in[9];  const float* bd = (const float*)d_in[10];
    float* out = (float*)d_out;

    cudaFuncSetAttribute(qkv_kernel, cudaFuncAttributeMaxDynamicSharedMemorySize, SMEM_DYN);
    cudaFuncSetAttribute(scores_kernel, cudaFuncAttributeMaxDynamicSharedMemorySize, SMEM_DYN);
    cudaFuncSetAttribute(ctx_kernel, cudaFuncAttributeMaxDynamicSharedMemorySize, CTX_SMEM);
    cudaFuncSetAttribute(out_kernel, cudaFuncAttributeMaxDynamicSharedMemorySize, SMEM_DYN);

    dim3 blk(256);
    cvt_all_kernel<<<8192 + 4 * 4096, blk>>>(X, Wq, Wk, Wv, Wd);

    qkv_kernel<<<dim3(16, 32, 3), blk, SMEM_DYN>>>(bq, bk, bv);
    scores_kernel<<<dim3(16, 16, 32), blk, SMEM_DYN>>>(alibi);
    ctx_kernel<<<dim3(1, 16, 32), blk, CTX_SMEM>>>();
    out_kernel<<<dim3(16, 32), blk, SMEM_DYN>>>(bd, residual, out);
}

// round 11
// speedup vs baseline: 1.3609x; 1.0548x over previous
#include <cuda_runtime.h>
#include <cuda_bf16.h>
#include <cuda_fp16.h>
#include <math.h>
#include <stdint.h>

#define HIDDEN   2048
#define NHEADS   16
#define HDIM     128
#define BATCH    2
#define SEQ      2048
#define BH       (BATCH * NHEADS)
#define MROWS    (BATCH * SEQ)
#define INV_NORM 0.08838834764831845f   // 1/sqrt(128)

#define KB        32
#define STAGE_B   32768
#define NSTAGE    3
#define EPI_STR   132
#define SMEM_DYN  (NSTAGE * STAGE_B)     // 98304

// ctx: 3 stages x 24KB (P 8K | Vh 8K | Vl 8K) + rowsum
#define CSTG_B    24576
#define CTX_RS    (3 * CSTG_B)           // 73728
#define CTX_SMEM  74240

// ===================== scratch (static __device__, no allocation) ============
__device__ __align__(128) __half g_ph[(size_t)BH * SEQ * SEQ];          // 256MB
__device__ __align__(128) float g_psum[(size_t)BH * 16 * SEQ];          // 4MB

__device__ __align__(128) __nv_bfloat16 g_xh[(size_t)MROWS * HIDDEN];
__device__ __align__(128) __nv_bfloat16 g_xl[(size_t)MROWS * HIDDEN];
__device__ __align__(128) __nv_bfloat16 g_wqh[(size_t)HIDDEN * HIDDEN];
__device__ __align__(128) __nv_bfloat16 g_wql[(size_t)HIDDEN * HIDDEN];
__device__ __align__(128) __nv_bfloat16 g_wkh[(size_t)HIDDEN * HIDDEN];
__device__ __align__(128) __nv_bfloat16 g_wkl[(size_t)HIDDEN * HIDDEN];
__device__ __align__(128) __nv_bfloat16 g_wvh[(size_t)HIDDEN * HIDDEN];
__device__ __align__(128) __nv_bfloat16 g_wvl[(size_t)HIDDEN * HIDDEN];
__device__ __align__(128) __nv_bfloat16 g_wdh[(size_t)HIDDEN * HIDDEN];
__device__ __align__(128) __nv_bfloat16 g_wdl[(size_t)HIDDEN * HIDDEN];

__device__ __align__(128) __nv_bfloat16 g_qh[(size_t)BH * SEQ * HDIM];
__device__ __align__(128) __nv_bfloat16 g_ql[(size_t)BH * SEQ * HDIM];
__device__ __align__(128) __nv_bfloat16 g_kh[(size_t)BH * SEQ * HDIM];
__device__ __align__(128) __nv_bfloat16 g_kl[(size_t)BH * SEQ * HDIM];
__device__ __align__(128) __half g_vTh[(size_t)BH * HDIM * SEQ];
__device__ __align__(128) __half g_vTl[(size_t)BH * HDIM * SEQ];
__device__ __align__(128) __nv_bfloat16 g_ch[(size_t)MROWS * HIDDEN];
__device__ __align__(128) __nv_bfloat16 g_cl[(size_t)MROWS * HIDDEN];

// ===================== helpers ===============================================
static __device__ __forceinline__ uint32_t s2u(const void* p) {
    uint32_t a;
    asm("{ .reg .u64 t; cvta.to.shared.u64 t, %1; cvt.u32.u64 %0, t; }"
        : "=r"(a) : "l"(p));
    return a;
}
static __device__ __forceinline__ void ldm4(uint32_t (&r)[4], uint32_t addr) {
    asm volatile("ldmatrix.sync.aligned.m8n8.x4.shared.b16 {%0,%1,%2,%3}, [%4];"
                 : "=r"(r[0]), "=r"(r[1]), "=r"(r[2]), "=r"(r[3]) : "r"(addr));
}
static __device__ __forceinline__ void mma16816(float (&c)[4],
                                                const uint32_t (&a)[4],
                                                const uint32_t* b) {
    asm volatile("mma.sync.aligned.m16n8k16.row.col.f32.bf16.bf16.f32 "
                 "{%0,%1,%2,%3}, {%4,%5,%6,%7}, {%8,%9}, {%0,%1,%2,%3};"
                 : "+f"(c[0]), "+f"(c[1]), "+f"(c[2]), "+f"(c[3])
                 : "r"(a[0]), "r"(a[1]), "r"(a[2]), "r"(a[3]),
                   "r"(b[0]), "r"(b[1]));
}
static __device__ __forceinline__ void mma16816h(float (&c)[4],
                                                 const uint32_t (&a)[4],
                                                 const uint32_t* b) {
    asm volatile("mma.sync.aligned.m16n8k16.row.col.f32.f16.f16.f32 "
                 "{%0,%1,%2,%3}, {%4,%5,%6,%7}, {%8,%9}, {%0,%1,%2,%3};"
                 : "+f"(c[0]), "+f"(c[1]), "+f"(c[2]), "+f"(c[3])
                 : "r"(a[0]), "r"(a[1]), "r"(a[2]), "r"(a[3]),
                   "r"(b[0]), "r"(b[1]));
}
static __device__ __forceinline__ void split_bf(float x, __nv_bfloat16& h,
                                                __nv_bfloat16& l) {
    h = __float2bfloat16(x);
    l = __float2bfloat16(x - __bfloat162float(h));
}
static __device__ __forceinline__ void split_h(float x, __half& h, __half& l) {
    h = __float2half(x);
    l = __float2half(x - __half2float(h));
}
static __device__ __forceinline__ void cpa16(uint32_t so, const void* g) {
    asm volatile("cp.async.cg.shared.global [%0], [%1], 16;" :: "r"(so), "l"(g));
}
static __device__ __forceinline__ uint32_t swz(int row, int c16) {       // 64B rows
    return (uint32_t)(row * 64 + ((c16 ^ ((row >> 1) & 3)) << 4));
}

// one warp's 12-MMA bundle for a 16-row A slab (hi+lo) against cached B frags
static __device__ __forceinline__ void mma_slab(
    float (&accm)[4][4], uint32_t aAddrH, uint32_t aAddrL,
    const uint32_t (&bH)[2][4], const uint32_t (&bL)[2][4]) {
    uint32_t aH4[4], aL4[4];
    ldm4(aH4, aAddrH);
    ldm4(aL4, aAddrL);
#pragma unroll
    for (int ni = 0; ni < 4; ni++) {
        const uint32_t* bh2 = &bH[ni >> 1][(ni & 1) * 2];
        const uint32_t* bl2 = &bL[ni >> 1][(ni & 1) * 2];
        mma16816(accm[ni], aH4, bh2);
        mma16816(accm[ni], aH4, bl2);
        mma16816(accm[ni], aL4, bh2);
    }
}

// ===================== bf16x3 mma.sync GEMM core (128x128, 256 thr) ==========
static __device__ __forceinline__ void mma_gemm(
    const __nv_bfloat16* __restrict__ Ah, const __nv_bfloat16* __restrict__ Al,
    const __nv_bfloat16* __restrict__ Bh, const __nv_bfloat16* __restrict__ Bl,
    int K, int lda, int ldb, float (&acc)[4][4][4]) {
    extern __shared__ char smem[];
    const uint32_t sb = s2u(smem);
    const int tid  = threadIdx.x;
    const int lane = tid & 31;
    const int wid  = tid >> 5;
    const int wm   = wid & 1;
    const int wn   = wid >> 1;
    const int NC   = K >> 5;

    const __nv_bfloat16* srcs[4] = { Ah, Al, Bh, Bl };
    const int lds[4] = { lda, lda, ldb, ldb };
    const int lrow = tid >> 2;
    const int lc16 = tid & 3;

#define ISSUE(cc)                                                              \
    {                                                                          \
        const int _c = (cc);                                                   \
        const uint32_t sbase = sb + (_c % NSTAGE) * STAGE_B;                   \
        _Pragma("unroll")                                                      \
        for (int mat = 0; mat < 4; mat++) {                                    \
            _Pragma("unroll")                                                  \
            for (int rep = 0; rep < 2; rep++) {                                \
                const int row = lrow + rep * 64;                               \
                const char* g = (const char*)(srcs[mat] +                      \
                                  (size_t)row * lds[mat] + _c * KB) + lc16*16; \
                const uint32_t so = sbase + mat * 8192 + swz(row, lc16);       \
                cpa16(so, g);                                                  \
            }                                                                  \
        }                                                                      \
        asm volatile("cp.async.commit_group;" ::: "memory");                   \
    }

    ISSUE(0);
    if (NC > 1) ISSUE(1);

    const int arow_in = lane & 15;
    const int akh     = lane >> 4;
    const int brow_in = ((lane >> 4) << 3) + (lane & 7);
    const int bkh     = (lane >> 3) & 1;

    for (int c = 0; c < NC; c++) {
        if (c + 1 < NC) {
            asm volatile("cp.async.wait_group 1;" ::: "memory");
        } else {
            asm volatile("cp.async.wait_group 0;" ::: "memory");
        }
        __syncthreads();
        if (c + 2 < NC) ISSUE(c + 2);

        const uint32_t st = sb + (c % NSTAGE) * STAGE_B;
#pragma unroll
        for (int kk = 0; kk < 2; kk++) {
            uint32_t bH[2][4], bL[2][4];
#pragma unroll
            for (int nj = 0; nj < 2; nj++) {
                const int row = wn * 32 + nj * 16 + brow_in;
                const uint32_t bd = st + 16384 + swz(row, kk * 2 + bkh);
                ldm4(bH[nj], bd);
                ldm4(bL[nj], bd + 8192);
            }
#pragma unroll
            for (int mi = 0; mi < 4; mi++) {
                const int row = wm * 64 + mi * 16 + arow_in;
                const uint32_t ad = st + swz(row, kk * 2 + akh);
                mma_slab(acc[mi], ad, ad + 8192, bH, bL);
            }
        }
    }
    __syncthreads();
#undef ISSUE
}

static __device__ __forceinline__ void acc_to_smem(float (&acc)[4][4][4]) {
    extern __shared__ char smem[];
    float* ep = (float*)smem;
    const int lane = threadIdx.x & 31;
    const int wid  = threadIdx.x >> 5;
    const int wm = wid & 1, wn = wid >> 1;
#pragma unroll
    for (int mi = 0; mi < 4; mi++)
#pragma unroll
        for (int ni = 0; ni < 4; ni++) {
            const int r0 = wm * 64 + mi * 16 + (lane >> 2);
            const int c0 = wn * 32 + ni * 8 + (lane & 3) * 2;
            ep[r0 * EPI_STR + c0]           = acc[mi][ni][0];
            ep[r0 * EPI_STR + c0 + 1]       = acc[mi][ni][1];
            ep[(r0 + 8) * EPI_STR + c0]     = acc[mi][ni][2];
            ep[(r0 + 8) * EPI_STR + c0 + 1] = acc[mi][ni][3];
        }
    __syncthreads();
}

// ===================== fp32 -> bf16 hi/lo split (one launch for all) =========
__global__ void __launch_bounds__(256)
cvt_all_kernel(const float* __restrict__ X,  const float* __restrict__ Wq,
               const float* __restrict__ Wk, const float* __restrict__ Wv,
               const float* __restrict__ Wd) {
    const int bid = blockIdx.x;
    const float* src;
    __nv_bfloat16 *hi, *lo;
    int rel;
    if (bid < 8192)       { src = X;  hi = g_xh;  lo = g_xl;  rel = bid; }
    else {
        const int w = (bid - 8192) >> 12;
        rel = (bid - 8192) & 4095;
        switch (w) {
            case 0:  src = Wq; hi = g_wqh; lo = g_wql; break;
            case 1:  src = Wk; hi = g_wkh; lo = g_wkl; break;
            case 2:  src = Wv; hi = g_wvh; lo = g_wvl; break;
            default: src = Wd; hi = g_wdh; lo = g_wdl; break;
        }
    }
    const int i = rel * 256 + threadIdx.x;
    float4 v = ((const float4*)src)[i];
    __nv_bfloat16 h0, l0, h1, l1, h2, l2, h3, l3;
    split_bf(v.x, h0, l0); split_bf(v.y, h1, l1);
    split_bf(v.z, h2, l2); split_bf(v.w, h3, l3);
    __nv_bfloat162 hv[2] = { __nv_bfloat162(h0, h1), __nv_bfloat162(h2, h3) };
    __nv_bfloat162 lv[2] = { __nv_bfloat162(l0, l1), __nv_bfloat162(l2, l3) };
    *(uint2*)(hi + (size_t)i * 4) = *(uint2*)hv;
    *(uint2*)(lo + (size_t)i * 4) = *(uint2*)lv;
}

// ===================== 1) QKV projection =====================================
__global__ void __launch_bounds__(256, 2)
qkv_kernel(const float* __restrict__ pbq, const float* __restrict__ pbk,
           const float* __restrict__ pbv) {
    const int mode = blockIdx.z;
    const int m0 = blockIdx.y * 128, n0 = blockIdx.x * 128;
    const __nv_bfloat16* Wh = (mode == 0) ? g_wqh : (mode == 1) ? g_wkh : g_wvh;
    const __nv_bfloat16* Wl = (mode == 0) ? g_wql : (mode == 1) ? g_wkl : g_wvl;
    const float* bias = (mode == 0) ? pbq : (mode == 1) ? pbk : pbv;

    float acc[4][4][4] = {};
    mma_gemm(g_xh + (size_t)m0 * HIDDEN, g_xl + (size_t)m0 * HIDDEN,
             Wh + (size_t)n0 * HIDDEN, Wl + (size_t)n0 * HIDDEN,
             HIDDEN, HIDDEN, HIDDEN, acc);
    acc_to_smem(acc);

    extern __shared__ char smem[];
    const float* ep = (const float*)smem;
    const int tid = threadIdx.x;
    const int half = tid & 1;
    const int h = blockIdx.x;

    if (mode == 2) {
        // vT fp16 hi/lo: [bh][d][s]
        const int dcol = tid >> 1;
        const int b = m0 >> 11;
        const float bia = bias[n0 + dcol];
        const size_t base = ((size_t)(b * NHEADS + h) * HDIM + dcol) * SEQ +
                            (m0 & (SEQ - 1)) + half * 64;
#pragma unroll 8
        for (int s = 0; s < 64; s += 2) {
            float v0 = ep[(half * 64 + s) * EPI_STR + dcol] + bia;
            float v1 = ep[(half * 64 + s + 1) * EPI_STR + dcol] + bia;
            __half h0, l0, h1, l1;
            split_h(v0, h0, l0); split_h(v1, h1, l1);
            *(__half2*)(g_vTh + base + s) = __halves2half2(h0, h1);
            *(__half2*)(g_vTl + base + s) = __halves2half2(l0, l1);
        }
    } else {
        const int r = tid >> 1;
        const int m = m0 + r;
        const int b = m >> 11, s = m & (SEQ - 1);
        __nv_bfloat16* dh = (mode == 0) ? g_qh : g_kh;
        __nv_bfloat16* dl = (mode == 0) ? g_ql : g_kl;
        const size_t base = ((size_t)(b * NHEADS + h) * SEQ + s) * HDIM + half * 64;
        const float* er = ep + r * EPI_STR + half * 64;
        const float* bi = bias + n0 + half * 64;
#pragma unroll 8
        for (int cc = 0; cc < 64; cc += 2) {
            float v0 = er[cc] + bi[cc];
            float v1 = er[cc + 1] + bi[cc + 1];
            __nv_bfloat16 h0, l0, h1, l1;
            split_bf(v0, h0, l0); split_bf(v1, h1, l1);
            *(__nv_bfloat162*)(dh + base + cc) = __nv_bfloat162(h0, h1);
            *(__nv_bfloat162*)(dl + base + cc) = __nv_bfloat162(l0, l1);
        }
    }
}

// ===================== 2) scores -> P = exp(s) fp16 + partial row sums =======
__global__ void __launch_bounds__(256, 2)
scores_kernel(const float* __restrict__ alibi) {
    const int z = blockIdx.z;
    const int m0 = blockIdx.y * 128, n0 = blockIdx.x * 128;
    const size_t zo = (size_t)z * SEQ * HDIM;

    float acc[4][4][4] = {};
    mma_gemm(g_qh + zo + (size_t)m0 * HDIM, g_ql + zo + (size_t)m0 * HDIM,
             g_kh + zo + (size_t)n0 * HDIM, g_kl + zo + (size_t)n0 * HDIM,
             HDIM, HDIM, HDIM, acc);
    acc_to_smem(acc);

    extern __shared__ char smem[];
    const float* ep = (const float*)smem;
    const int tid = threadIdx.x;
    const int r = tid >> 1, half = tid & 1;
    const float* al = alibi + (size_t)z * SEQ + n0 + half * 64;
    const size_t prow = (size_t)z * SEQ * SEQ + (size_t)(m0 + r) * SEQ +
                        n0 + half * 64;
    const float* er = ep + r * EPI_STR + half * 64;

    float lsum = 0.f;
#pragma unroll 4
    for (int cc = 0; cc < 64; cc += 4) {
        float4 av = *(const float4*)(al + cc);
        float p0 = __expf(av.x + INV_NORM * er[cc + 0]);
        float p1 = __expf(av.y + INV_NORM * er[cc + 1]);
        float p2 = __expf(av.z + INV_NORM * er[cc + 2]);
        float p3 = __expf(av.w + INV_NORM * er[cc + 3]);
        lsum += (p0 + p1) + (p2 + p3);
        __half2 hv[2] = { __halves2half2(__float2half(p0), __float2half(p1)),
                          __halves2half2(__float2half(p2), __float2half(p3)) };
        *(uint2*)(g_ph + prow + cc) = *(uint2*)hv;
    }
    lsum += __shfl_xor_sync(0xffffffffu, lsum, 1);
    if (half == 0)
        g_psum[((size_t)z * 16 + blockIdx.x) * SEQ + m0 + r] = lsum;
}

// ===================== 3) ctx = P(fp16) @ (Vh+Vl), normalized ================
__global__ void __launch_bounds__(256, 2)
ctx_kernel() {
    extern __shared__ char smem[];
    const uint32_t sb = s2u(smem);
    const int tid  = threadIdx.x;
    const int lane = tid & 31;
    const int wid  = tid >> 5;
    const int wm   = wid & 1;
    const int wn   = wid >> 1;
    const int z    = blockIdx.z;
    const int m0   = blockIdx.y * 128;
    const size_t po = (size_t)z * SEQ * SEQ + (size_t)m0 * SEQ;
    const size_t vo = (size_t)z * HDIM * SEQ;
    const int NC = SEQ >> 5;     // 64

    // reduce 16 partial sums per row into smem rowsum[128]
    {
        const int row = tid >> 1, half = tid & 1;
        const float* ps = g_psum + (size_t)z * 16 * SEQ + m0 + row;
        float s = 0.f;
#pragma unroll
        for (int nb = 0; nb < 8; nb++) s += ps[(size_t)(half * 8 + nb) * SEQ];
        s += __shfl_xor_sync(0xffffffffu, s, 1);
        ((float*)(smem + CTX_RS))[row] = s;
    }

    const int lrow = tid >> 1;
    const int lc0  = (tid & 1) * 2;

#define CISSUE(cc)                                                             \
    {                                                                          \
        const int _c = (cc);                                                   \
        const uint32_t sbase = sb + (_c % NSTAGE) * CSTG_B;                    \
        const char* gp  = (const char*)(g_ph  + po + (size_t)lrow * SEQ +      \
                                        _c * 32);                              \
        const char* gvh = (const char*)(g_vTh + vo + (size_t)lrow * SEQ +      \
                                        _c * 32);                              \
        const char* gvl = (const char*)(g_vTl + vo + (size_t)lrow * SEQ +      \
                                        _c * 32);                              \
        _Pragma("unroll")                                                      \
        for (int u = 0; u < 2; u++) {                                          \
            const int c16 = lc0 + u;                                           \
            const uint32_t so = swz(lrow, c16);                                \
            cpa16(sbase + so,         gp  + c16 * 16);                         \
            cpa16(sbase + 8192 + so,  gvh + c16 * 16);                         \
            cpa16(sbase + 16384 + so, gvl + c16 * 16);                         \
        }                                                                      \
        asm volatile("cp.async.commit_group;" ::: "memory");                   \
    }

    CISSUE(0);
    CISSUE(1);

    const int arow_in = lane & 15;
    const int akh     = lane >> 4;
    const int brow_in = ((lane >> 4) << 3) + (lane & 7);
    const int bkh     = (lane >> 3) & 1;

    float acc[4][4][4] = {};

    for (int c = 0; c < NC; c++) {
        if (c + 1 < NC) {
            asm volatile("cp.async.wait_group 1;" ::: "memory");
        } else {
            asm volatile("cp.async.wait_group 0;" ::: "memory");
        }
        __syncthreads();
        if (c + 2 < NC) CISSUE(c + 2);

        const uint32_t st = sb + (c % NSTAGE) * CSTG_B;
#pragma unroll
        for (int kk = 0; kk < 2; kk++) {
            uint32_t bH[2][4], bL[2][4];
#pragma unroll
            for (int nj = 0; nj < 2; nj++) {
                const int row = wn * 32 + nj * 16 + brow_in;
                const uint32_t bd = st + swz(row, kk * 2 + bkh);
                ldm4(bH[nj], bd + 8192);
                ldm4(bL[nj], bd + 16384);
            }
#pragma unroll
            for (int mi = 0; mi < 4; mi++) {
                const int row = wm * 64 + mi * 16 + arow_in;
                uint32_t aP[4];
                ldm4(aP, st + swz(row, kk * 2 + akh));
#pragma unroll
                for (int ni = 0; ni < 4; ni++) {
                    mma16816h(acc[mi][ni], aP, &bH[ni >> 1][(ni & 1) * 2]);
                    mma16816h(acc[mi][ni], aP, &bL[ni >> 1][(ni & 1) * 2]);
                }
            }
        }
    }
#undef CISSUE
    __syncthreads();

    // normalize accumulators by 1/rowsum
    const float* rsm = (const float*)(smem + CTX_RS);
#pragma unroll
    for (int mi = 0; mi < 4; mi++) {
        const int r0 = wm * 64 + mi * 16 + (lane >> 2);
        const float inv0 = 1.0f / rsm[r0];
        const float inv1 = 1.0f / rsm[r0 + 8];
#pragma unroll
        for (int ni = 0; ni < 4; ni++) {
            acc[mi][ni][0] *= inv0;
            acc[mi][ni][1] *= inv0;
            acc[mi][ni][2] *= inv1;
            acc[mi][ni][3] *= inv1;
        }
    }
    acc_to_smem(acc);

    const float* ep = (const float*)smem;
    const int r = tid >> 1, half = tid & 1;
    const int b = z / NHEADS, h = z % NHEADS;
    const size_t base = ((size_t)(b * SEQ + m0 + r)) * HIDDEN +
                        h * HDIM + half * 64;
    const float* er = ep + r * EPI_STR + half * 64;
#pragma unroll 8
    for (int cc = 0; cc < 64; cc += 2) {
        __nv_bfloat16 h0, l0, h1, l1;
        split_bf(er[cc], h0, l0); split_bf(er[cc + 1], h1, l1);
        *(__nv_bfloat162*)(g_ch + base + cc) = __nv_bfloat162(h0, h1);
        *(__nv_bfloat162*)(g_cl + base + cc) = __nv_bfloat162(l0, l1);
    }
}

// ===================== 4) out = ctx @ Wd^T + bd + residual ===================
__global__ void __launch_bounds__(256, 2)
out_kernel(const float* __restrict__ bd, const float* __restrict__ residual,
           float* __restrict__ outp) {
    const int m0 = blockIdx.y * 128, n0 = blockIdx.x * 128;

    float acc[4][4][4] = {};
    mma_gemm(g_ch + (size_t)m0 * HIDDEN, g_cl + (size_t)m0 * HIDDEN,
             g_wdh + (size_t)n0 * HIDDEN, g_wdl + (size_t)n0 * HIDDEN,
             HIDDEN, HIDDEN, HIDDEN, acc);
    acc_to_smem(acc);

    extern __shared__ char smem[];
    const float* ep = (const float*)smem;
    const int tid = threadIdx.x;
    const int r = tid >> 1, half = tid & 1;
    const size_t idx = (size_t)(m0 + r) * HIDDEN + n0 + half * 64;
    const float* er = ep + r * EPI_STR + half * 64;
    const float* bi = bd + n0 + half * 64;
    const float* rs = residual + idx;
    float* dst = outp + idx;
#pragma unroll 4
    for (int cc = 0; cc < 64; cc += 4) {
        float4 bv = *(const float4*)(bi + cc);
        float4 rv = *(const float4*)(rs + cc);
        float4 v;
        v.x = er[cc + 0] + bv.x + rv.x;
        v.y = er[cc + 1] + bv.y + rv.y;
        v.z = er[cc + 2] + bv.z + rv.z;
        v.w = er[cc + 3] + bv.w + rv.w;
        *(float4*)(dst + cc) = v;
    }
}

// ===================== launch =================================================
extern "C" void kernel_launch(void* const* d_in, const int* in_sizes, int n_in,
                              void* d_out, int out_size) {
    const float* X        = (const float*)d_in[0];
    const float* residual = (const float*)d_in[1];
    const float* alibi    = (const float*)d_in[2];
    const float* Wq = (const float*)d_in[3];  const float* bq = (const float*)d_in[4];
    const float* Wk = (const float*)d_in[5];  const float* bk = (const float*)d_in[6];
    const float* Wv = (const float*)d_in[7];  const float* bv = (const float*)d_in[8];
    const float* Wd = (const float*)d_in[9];  const float* bd = (const float*)d_in[10];
    float* out = (float*)d_out;

    cudaFuncSetAttribute(qkv_kernel, cudaFuncAttributeMaxDynamicSharedMemorySize, SMEM_DYN);
    cudaFuncSetAttribute(scores_kernel, cudaFuncAttributeMaxDynamicSharedMemorySize, SMEM_DYN);
    cudaFuncSetAttribute(ctx_kernel, cudaFuncAttributeMaxDynamicSharedMemorySize, CTX_SMEM);
    cudaFuncSetAttribute(out_kernel, cudaFuncAttributeMaxDynamicSharedMemorySize, SMEM_DYN);

    dim3 blk(256);
    cvt_all_kernel<<<8192 + 4 * 4096, blk>>>(X, Wq, Wk, Wv, Wd);

    qkv_kernel<<<dim3(16, 32, 3), blk, SMEM_DYN>>>(bq, bk, bv);
    scores_kernel<<<dim3(16, 16, 32), blk, SMEM_DYN>>>(alibi);
    ctx_kernel<<<dim3(1, 16, 32), blk, CTX_SMEM>>>();
    out_kernel<<<dim3(16, 32), blk, SMEM_DYN>>>(bd, residual, out);
}

// round 12
// speedup vs baseline: 2.3338x; 1.7149x over previous
#include <cuda_runtime.h>
#include <cuda_fp16.h>
#include <math.h>
#include <stdint.h>

#define HIDDEN   2048
#define NHEADS   16
#define HDIM     128
#define BATCH    2
#define SEQ      2048
#define BH       (BATCH * NHEADS)
#define MROWS    (BATCH * SEQ)
#define INV_NORM 0.08838834764831845f   // 1/sqrt(128)

#define STAGE_B   16384                  // A 8K | B 8K  (fp16 single)
#define NSTAGE    3
#define EPI_STR   132
#define SMEM_DYN  67584                  // max(3*16384, 128*132*4)

#define CTX_RS    67584
#define CTX_SMEM  68096

// ===================== scratch (static __device__, no allocation) ============
__device__ __align__(128) __half g_p[(size_t)BH * SEQ * SEQ];           // 256MB
__device__ __align__(128) float g_psum[(size_t)BH * 16 * SEQ];          // 4MB

__device__ __align__(128) __half g_x[(size_t)MROWS * HIDDEN];
__device__ __align__(128) __half g_wq[(size_t)HIDDEN * HIDDEN];
__device__ __align__(128) __half g_wk[(size_t)HIDDEN * HIDDEN];
__device__ __align__(128) __half g_wv[(size_t)HIDDEN * HIDDEN];
__device__ __align__(128) __half g_wd[(size_t)HIDDEN * HIDDEN];

__device__ __align__(128) __half g_q[(size_t)BH * SEQ * HDIM];
__device__ __align__(128) __half g_k[(size_t)BH * SEQ * HDIM];
__device__ __align__(128) __half g_vT[(size_t)BH * HDIM * SEQ];
__device__ __align__(128) __half g_c[(size_t)MROWS * HIDDEN];

// ===================== helpers ===============================================
static __device__ __forceinline__ uint32_t s2u(const void* p) {
    uint32_t a;
    asm("{ .reg .u64 t; cvta.to.shared.u64 t, %1; cvt.u32.u64 %0, t; }"
        : "=r"(a) : "l"(p));
    return a;
}
static __device__ __forceinline__ void ldm4(uint32_t (&r)[4], uint32_t addr) {
    asm volatile("ldmatrix.sync.aligned.m8n8.x4.shared.b16 {%0,%1,%2,%3}, [%4];"
                 : "=r"(r[0]), "=r"(r[1]), "=r"(r[2]), "=r"(r[3]) : "r"(addr));
}
static __device__ __forceinline__ void mma16816h(float (&c)[4],
                                                 const uint32_t (&a)[4],
                                                 const uint32_t* b) {
    asm volatile("mma.sync.aligned.m16n8k16.row.col.f32.f16.f16.f32 "
                 "{%0,%1,%2,%3}, {%4,%5,%6,%7}, {%8,%9}, {%0,%1,%2,%3};"
                 : "+f"(c[0]), "+f"(c[1]), "+f"(c[2]), "+f"(c[3])
                 : "r"(a[0]), "r"(a[1]), "r"(a[2]), "r"(a[3]),
                   "r"(b[0]), "r"(b[1]));
}
static __device__ __forceinline__ void cpa16(uint32_t so, const void* g) {
    asm volatile("cp.async.cg.shared.global [%0], [%1], 16;" :: "r"(so), "l"(g));
}
static __device__ __forceinline__ uint32_t swz(int row, int c16) {       // 64B rows
    return (uint32_t)(row * 64 + ((c16 ^ ((row >> 1) & 3)) << 4));
}

// ===================== fp16 mma.sync GEMM core (128x128, 256 thr) ============
// C[128x128] = A[128xK] @ B[128xK]^T, fp16 single operands, fp32 acc. NT.
static __device__ __forceinline__ void mma_gemm_h(
    const __half* __restrict__ A, const __half* __restrict__ B,
    int K, int lda, int ldb, float (&acc)[4][4][4]) {
    extern __shared__ char smem[];
    const uint32_t sb = s2u(smem);
    const int tid  = threadIdx.x;
    const int lane = tid & 31;
    const int wid  = tid >> 5;
    const int wm   = wid & 1;
    const int wn   = wid >> 1;
    const int NC   = K >> 5;

    const int lrow = tid >> 1;           // 0..127
    const int lc0  = (tid & 1) * 2;      // 2 x 16B per thread per tile

#define ISSUE(cc)                                                              \
    {                                                                          \
        const int _c = (cc);                                                   \
        const uint32_t sbase = sb + (_c % NSTAGE) * STAGE_B;                   \
        const char* ga = (const char*)(A + (size_t)lrow * lda + _c * 32);      \
        const char* gb = (const char*)(B + (size_t)lrow * ldb + _c * 32);      \
        _Pragma("unroll")                                                      \
        for (int u = 0; u < 2; u++) {                                          \
            const int c16 = lc0 + u;                                           \
            const uint32_t so = swz(lrow, c16);                                \
            cpa16(sbase + so,        ga + c16 * 16);                           \
            cpa16(sbase + 8192 + so, gb + c16 * 16);                           \
        }                                                                      \
        asm volatile("cp.async.commit_group;" ::: "memory");                   \
    }

    ISSUE(0);
    if (NC > 1) ISSUE(1);

    const int arow_in = lane & 15;
    const int akh     = lane >> 4;
    const int brow_in = ((lane >> 4) << 3) + (lane & 7);
    const int bkh     = (lane >> 3) & 1;

    for (int c = 0; c < NC; c++) {
        if (c + 1 < NC) {
            asm volatile("cp.async.wait_group 1;" ::: "memory");
        } else {
            asm volatile("cp.async.wait_group 0;" ::: "memory");
        }
        __syncthreads();
        if (c + 2 < NC) ISSUE(c + 2);

        const uint32_t st = sb + (c % NSTAGE) * STAGE_B;
#pragma unroll
        for (int kk = 0; kk < 2; kk++) {
            uint32_t bF[2][4];
#pragma unroll
            for (int nj = 0; nj < 2; nj++) {
                const int row = wn * 32 + nj * 16 + brow_in;
                ldm4(bF[nj], st + 8192 + swz(row, kk * 2 + bkh));
            }
#pragma unroll
            for (int mi = 0; mi < 4; mi++) {
                const int row = wm * 64 + mi * 16 + arow_in;
                uint32_t aF[4];
                ldm4(aF, st + swz(row, kk * 2 + akh));
#pragma unroll
                for (int ni = 0; ni < 4; ni++)
                    mma16816h(acc[mi][ni], aF, &bF[ni >> 1][(ni & 1) * 2]);
            }
        }
    }
    __syncthreads();
#undef ISSUE
}

static __device__ __forceinline__ void acc_to_smem(float (&acc)[4][4][4]) {
    extern __shared__ char smem[];
    float* ep = (float*)smem;
    const int lane = threadIdx.x & 31;
    const int wid  = threadIdx.x >> 5;
    const int wm = wid & 1, wn = wid >> 1;
#pragma unroll
    for (int mi = 0; mi < 4; mi++)
#pragma unroll
        for (int ni = 0; ni < 4; ni++) {
            const int r0 = wm * 64 + mi * 16 + (lane >> 2);
            const int c0 = wn * 32 + ni * 8 + (lane & 3) * 2;
            ep[r0 * EPI_STR + c0]           = acc[mi][ni][0];
            ep[r0 * EPI_STR + c0 + 1]       = acc[mi][ni][1];
            ep[(r0 + 8) * EPI_STR + c0]     = acc[mi][ni][2];
            ep[(r0 + 8) * EPI_STR + c0 + 1] = acc[mi][ni][3];
        }
    __syncthreads();
}

// ===================== fp32 -> fp16 convert (one launch for all) =============
__global__ void __launch_bounds__(256)
cvt_all_kernel(const float* __restrict__ X,  const float* __restrict__ Wq,
               const float* __restrict__ Wk, const float* __restrict__ Wv,
               const float* __restrict__ Wd) {
    const int bid = blockIdx.x;
    const float* src;
    __half* dst;
    int rel;
    if (bid < 8192)       { src = X;  dst = g_x;  rel = bid; }
    else {
        const int w = (bid - 8192) >> 12;
        rel = (bid - 8192) & 4095;
        switch (w) {
            case 0:  src = Wq; dst = g_wq; break;
            case 1:  src = Wk; dst = g_wk; break;
            case 2:  src = Wv; dst = g_wv; break;
            default: src = Wd; dst = g_wd; break;
        }
    }
    const int i = rel * 256 + threadIdx.x;
    float4 v = ((const float4*)src)[i];
    __half2 hv[2] = { __halves2half2(__float2half(v.x), __float2half(v.y)),
                      __halves2half2(__float2half(v.z), __float2half(v.w)) };
    *(uint2*)(dst + (size_t)i * 4) = *(uint2*)hv;
}

// ===================== 1) QKV projection =====================================
__global__ void __launch_bounds__(256, 2)
qkv_kernel(const float* __restrict__ pbq, const float* __restrict__ pbk,
           const float* __restrict__ pbv) {
    const int mode = blockIdx.z;
    const int m0 = blockIdx.y * 128, n0 = blockIdx.x * 128;
    const __half* W = (mode == 0) ? g_wq : (mode == 1) ? g_wk : g_wv;
    const float* bias = (mode == 0) ? pbq : (mode == 1) ? pbk : pbv;

    float acc[4][4][4] = {};
    mma_gemm_h(g_x + (size_t)m0 * HIDDEN, W + (size_t)n0 * HIDDEN,
               HIDDEN, HIDDEN, HIDDEN, acc);
    acc_to_smem(acc);

    extern __shared__ char smem[];
    const float* ep = (const float*)smem;
    const int tid = threadIdx.x;
    const int half = tid & 1;
    const int h = blockIdx.x;

    if (mode == 2) {
        // vT: [bh][d][s]
        const int dcol = tid >> 1;
        const int b = m0 >> 11;
        const float bia = bias[n0 + dcol];
        const size_t base = ((size_t)(b * NHEADS + h) * HDIM + dcol) * SEQ +
                            (m0 & (SEQ - 1)) + half * 64;
#pragma unroll 8
        for (int s = 0; s < 64; s += 2) {
            float v0 = ep[(half * 64 + s) * EPI_STR + dcol] + bia;
            float v1 = ep[(half * 64 + s + 1) * EPI_STR + dcol] + bia;
            *(__half2*)(g_vT + base + s) =
                __halves2half2(__float2half(v0), __float2half(v1));
        }
    } else {
        const int r = tid >> 1;
        const int m = m0 + r;
        const int b = m >> 11, s = m & (SEQ - 1);
        __half* dq = (mode == 0) ? g_q : g_k;
        const size_t base = ((size_t)(b * NHEADS + h) * SEQ + s) * HDIM + half * 64;
        const float* er = ep + r * EPI_STR + half * 64;
        const float* bi = bias + n0 + half * 64;
#pragma unroll 8
        for (int cc = 0; cc < 64; cc += 2) {
            float v0 = er[cc] + bi[cc];
            float v1 = er[cc + 1] + bi[cc + 1];
            *(__half2*)(dq + base + cc) =
                __halves2half2(__float2half(v0), __float2half(v1));
        }
    }
}

// ===================== 2) scores -> P = exp(s) fp16 + partial row sums =======
__global__ void __launch_bounds__(256, 2)
scores_kernel(const float* __restrict__ alibi) {
    const int z = blockIdx.z;
    const int m0 = blockIdx.y * 128, n0 = blockIdx.x * 128;
    const size_t zo = (size_t)z * SEQ * HDIM;

    float acc[4][4][4] = {};
    mma_gemm_h(g_q + zo + (size_t)m0 * HDIM, g_k + zo + (size_t)n0 * HDIM,
               HDIM, HDIM, HDIM, acc);
    acc_to_smem(acc);

    extern __shared__ char smem[];
    const float* ep = (const float*)smem;
    const int tid = threadIdx.x;
    const int r = tid >> 1, half = tid & 1;
    const float* al = alibi + (size_t)z * SEQ + n0 + half * 64;
    const size_t prow = (size_t)z * SEQ * SEQ + (size_t)(m0 + r) * SEQ +
                        n0 + half * 64;
    const float* er = ep + r * EPI_STR + half * 64;

    float lsum = 0.f;
#pragma unroll 4
    for (int cc = 0; cc < 64; cc += 4) {
        float4 av = *(const float4*)(al + cc);
        float p0 = __expf(av.x + INV_NORM * er[cc + 0]);
        float p1 = __expf(av.y + INV_NORM * er[cc + 1]);
        float p2 = __expf(av.z + INV_NORM * er[cc + 2]);
        float p3 = __expf(av.w + INV_NORM * er[cc + 3]);
        lsum += (p0 + p1) + (p2 + p3);
        __half2 hv[2] = { __halves2half2(__float2half(p0), __float2half(p1)),
                          __halves2half2(__float2half(p2), __float2half(p3)) };
        *(uint2*)(g_p + prow + cc) = *(uint2*)hv;
    }
    lsum += __shfl_xor_sync(0xffffffffu, lsum, 1);
    if (half == 0)
        g_psum[((size_t)z * 16 + blockIdx.x) * SEQ + m0 + r] = lsum;
}

// ===================== 3) ctx = P @ V, normalized ============================
__global__ void __launch_bounds__(256, 2)
ctx_kernel() {
    extern __shared__ char smem[];
    const int tid = threadIdx.x;
    const int z = blockIdx.z;
    const int m0 = blockIdx.y * 128;

    // reduce 16 partial sums per row into smem rowsum[128]
    {
        const int row = tid >> 1, half = tid & 1;
        const float* ps = g_psum + (size_t)z * 16 * SEQ + m0 + row;
        float s = 0.f;
#pragma unroll
        for (int nb = 0; nb < 8; nb++) s += ps[(size_t)(half * 8 + nb) * SEQ];
        s += __shfl_xor_sync(0xffffffffu, s, 1);
        ((float*)(smem + CTX_RS))[row] = s;
    }

    const size_t po = (size_t)z * SEQ * SEQ + (size_t)m0 * SEQ;
    const size_t vo = (size_t)z * HDIM * SEQ;
    float acc[4][4][4] = {};
    mma_gemm_h(g_p + po, g_vT + vo, SEQ, SEQ, SEQ, acc);

    // normalize accumulators by 1/rowsum
    const int lane = tid & 31, wid = tid >> 5;
    const int wm = wid & 1;
    const float* rsm = (const float*)(smem + CTX_RS);
#pragma unroll
    for (int mi = 0; mi < 4; mi++) {
        const int r0 = wm * 64 + mi * 16 + (lane >> 2);
        const float inv0 = 1.0f / rsm[r0];
        const float inv1 = 1.0f / rsm[r0 + 8];
#pragma unroll
        for (int ni = 0; ni < 4; ni++) {
            acc[mi][ni][0] *= inv0;
            acc[mi][ni][1] *= inv0;
            acc[mi][ni][2] *= inv1;
            acc[mi][ni][3] *= inv1;
        }
    }
    acc_to_smem(acc);

    const float* ep = (const float*)smem;
    const int r = tid >> 1, half = tid & 1;
    const int b = z / NHEADS, h = z % NHEADS;
    const size_t base = ((size_t)(b * SEQ + m0 + r)) * HIDDEN +
                        h * HDIM + half * 64;
    const float* er = ep + r * EPI_STR + half * 64;
#pragma unroll 8
    for (int cc = 0; cc < 64; cc += 2) {
        *(__half2*)(g_c + base + cc) =
            __halves2half2(__float2half(er[cc]), __float2half(er[cc + 1]));
    }
}

// ===================== 4) out = ctx @ Wd^T + bd + residual ===================
__global__ void __launch_bounds__(256, 2)
out_kernel(const float* __restrict__ bd, const float* __restrict__ residual,
           float* __restrict__ outp) {
    const int m0 = blockIdx.y * 128, n0 = blockIdx.x * 128;

    float acc[4][4][4] = {};
    mma_gemm_h(g_c + (size_t)m0 * HIDDEN, g_wd + (size_t)n0 * HIDDEN,
               HIDDEN, HIDDEN, HIDDEN, acc);
    acc_to_smem(acc);

    extern __shared__ char smem[];
    const float* ep = (const float*)smem;
    const int tid = threadIdx.x;
    const int r = tid >> 1, half = tid & 1;
    const size_t idx = (size_t)(m0 + r) * HIDDEN + n0 + half * 64;
    const float* er = ep + r * EPI_STR + half * 64;
    const float* bi = bd + n0 + half * 64;
    const float* rs = residual + idx;
    float* dst = outp + idx;
#pragma unroll 4
    for (int cc = 0; cc < 64; cc += 4) {
        float4 bv = *(const float4*)(bi + cc);
        float4 rv = *(const float4*)(rs + cc);
        float4 v;
        v.x = er[cc + 0] + bv.x + rv.x;
        v.y = er[cc + 1] + bv.y + rv.y;
        v.z = er[cc + 2] + bv.z + rv.z;
        v.w = er[cc + 3] + bv.w + rv.w;
        *(float4*)(dst + cc) = v;
    }
}

// ===================== launch =================================================
extern "C" void kernel_launch(void* const* d_in, const int* in_sizes, int n_in,
                              void* d_out, int out_size) {
    const float* X        = (const float*)d_in[0];
    const float* residual = (const float*)d_in[1];
    const float* alibi    = (const float*)d_in[2];
    const float* Wq = (const float*)d_in[3];  const float* bq = (const float*)d_in[4];
    const float* Wk = (const float*)d_in[5];  const float* bk = (const float*)d_in[6];
    const float* Wv = (const float*)d_in[7];  const float* bv = (const float*)d_in[8];
    const float* Wd = (const float*)d_in[9];  const float* bd = (const float*)d_in[10];
    float* out = (float*)d_out;

    cudaFuncSetAttribute(qkv_kernel, cudaFuncAttributeMaxDynamicSharedMemorySize, SMEM_DYN);
    cudaFuncSetAttribute(scores_kernel, cudaFuncAttributeMaxDynamicSharedMemorySize, SMEM_DYN);
    cudaFuncSetAttribute(ctx_kernel, cudaFuncAttributeMaxDynamicSharedMemorySize, CTX_SMEM);
    cudaFuncSetAttribute(out_kernel, cudaFuncAttributeMaxDynamicSharedMemorySize, SMEM_DYN);

    dim3 blk(256);
    cvt_all_kernel<<<8192 + 4 * 4096, blk>>>(X, Wq, Wk, Wv, Wd);

    qkv_kernel<<<dim3(16, 32, 3), blk, SMEM_DYN>>>(bq, bk, bv);
    scores_kernel<<<dim3(16, 16, 32), blk, SMEM_DYN>>>(alibi);
    ctx_kernel<<<dim3(1, 16, 32), blk, CTX_SMEM>>>();
    out_kernel<<<dim3(16, 32), blk, SMEM_DYN>>>(bd, residual, out);
}